// round 8
// baseline (speedup 1.0000x reference)
#include <cuda_runtime.h>
#include <cuda_bf16.h>
#include <cstdint>
#include <cstddef>

// ===========================================================================
// VQ nearest-codebook via warp-level HMMA (mma.sync m16n8k16 bf16).
//   argmin_k ||x-e_k||^2 == argmin_k (0.5||e_k||^2 - x.e_k)
// dot via bf16 3-way split folded into one K=768 GEMM:
//   A' = [xh | xh | xl],  B' = [eh | el | eh]
// R8: 8 warps (4m x 2n, warp tile 32x64) + cross-chunk fragment prefetch:
// ks0 frags of chunk c+1 are loaded at the END of chunk c (other buffer),
// so MMAs restart immediately after the barrier. Barrier placed between the
// last ldsm of a buffer and its overwrite; ks3 MMAs shadow the barrier.
// ===========================================================================

#define VQ_D   256
#define VQ_K   4096
#define VQ_BT  16384
#define BETA   0.2

#define BM   128
#define BN   128
#define KE   768                  // expanded K (bf16 elements)
#define KCH  12                   // k-chunks per n-chunk (64 bf16 = 128 B each)
#define NCH  (VQ_K / BN)          // 32
#define TOTCH (NCH * KCH)         // 384
#define NTH  256

#define ASTR  1552                // A smem row stride bytes (97*16, data 1536)
#define SMA_BYTES (128 * ASTR)    // 198656
#define SMB_BYTES 16384           // 128 rows x 128 B, SW128 swizzled
#define NBUF  2
#define SM_TOTAL (SMA_BYTES + NBUF * SMB_BYTES)   // 231424 <= 232448

// ---------------- device globals -------------------------------------------
__device__ float    g_cnorm[VQ_K];
__device__ int      g_idx[VQ_BT];
__device__ double   g_lossacc;
__device__ uint32_t g_ecat[VQ_K * (KE / 2)];    // [4096][768] bf16
__device__ uint32_t g_xcat[VQ_BT * (KE / 2)];   // [16384][768] bf16

// ---------------- helpers ---------------------------------------------------
__device__ __forceinline__ uint32_t smem_to_u32(const void* p) {
    uint32_t a;
    asm("{ .reg .u64 t; cvta.to.shared.u64 t, %1; cvt.u32.u64 %0, t; }"
        : "=r"(a) : "l"(p));
    return a;
}
__device__ __forceinline__ void cp16(uint32_t dst, size_t gsrc) {
    asm volatile("cp.async.cg.shared.global [%0], [%1], 16;"
                 :: "r"(dst), "l"(gsrc));
}
__device__ __forceinline__ void ldsm4(uint32_t* r, uint32_t addr) {
    asm volatile("ldmatrix.sync.aligned.m8n8.x4.shared.b16 {%0,%1,%2,%3}, [%4];"
                 : "=r"(r[0]), "=r"(r[1]), "=r"(r[2]), "=r"(r[3]) : "r"(addr));
}
__device__ __forceinline__ void mma16816(float* c, const uint32_t* a,
                                         uint32_t b0, uint32_t b1) {
    asm volatile(
        "mma.sync.aligned.m16n8k16.row.col.f32.bf16.bf16.f32 "
        "{%0,%1,%2,%3}, {%4,%5,%6,%7}, {%8,%9}, {%0,%1,%2,%3};"
        : "+f"(c[0]), "+f"(c[1]), "+f"(c[2]), "+f"(c[3])
        : "r"(a[0]), "r"(a[1]), "r"(a[2]), "r"(a[3]), "r"(b0), "r"(b1));
}

// ---------------------------------------------------------------------------
// Prep kernels
// ---------------------------------------------------------------------------
__global__ void vq_norms(const float* __restrict__ emb) {
    if (blockIdx.x == 0 && threadIdx.x == 0) g_lossacc = 0.0;
    int warp = (blockIdx.x * blockDim.x + threadIdx.x) >> 5;
    int lane = threadIdx.x & 31;
    if (warp >= VQ_K) return;
    const float4* e4 = reinterpret_cast<const float4*>(emb) + (size_t)warp * (VQ_D / 4);
    float s = 0.f;
    #pragma unroll
    for (int i = lane; i < VQ_D / 4; i += 32) {
        float4 v = e4[i];
        s += v.x * v.x + v.y * v.y + v.z * v.z + v.w * v.w;
    }
    #pragma unroll
    for (int o = 16; o; o >>= 1) s += __shfl_xor_sync(0xffffffffu, s, o);
    if (lane == 0) g_cnorm[warp] = 0.5f * s;
}

__device__ __forceinline__ void split4(float4 v, uint32_t& h01, uint32_t& h23,
                                       uint32_t& l01, uint32_t& l23) {
    __nv_bfloat162 h, l;
    h.x = __float2bfloat16_rn(v.x);
    h.y = __float2bfloat16_rn(v.y);
    l.x = __float2bfloat16_rn(v.x - __bfloat162float(h.x));
    l.y = __float2bfloat16_rn(v.y - __bfloat162float(h.y));
    h01 = *reinterpret_cast<uint32_t*>(&h);
    l01 = *reinterpret_cast<uint32_t*>(&l);
    h.x = __float2bfloat16_rn(v.z);
    h.y = __float2bfloat16_rn(v.w);
    l.x = __float2bfloat16_rn(v.z - __bfloat162float(h.x));
    l.y = __float2bfloat16_rn(v.w - __bfloat162float(h.y));
    h23 = *reinterpret_cast<uint32_t*>(&h);
    l23 = *reinterpret_cast<uint32_t*>(&l);
}

// emb rows: [ eh(256) | el(256) | eh(256) ]
__global__ void vq_prep_emb(const float* __restrict__ emb) {
    int i = blockIdx.x * blockDim.x + threadIdx.x;
    if (i >= VQ_K * (VQ_D / 4)) return;
    int k = i >> 6, d4 = i & 63;
    float4 v = reinterpret_cast<const float4*>(emb)[i];
    uint32_t h01, h23, l01, l23;
    split4(v, h01, h23, l01, l23);
    uint32_t* row = g_ecat + (size_t)k * (KE / 2);
    row[d4 * 2]       = h01; row[d4 * 2 + 1]       = h23;
    row[128 + d4 * 2] = l01; row[128 + d4 * 2 + 1] = l23;
    row[256 + d4 * 2] = h01; row[256 + d4 * 2 + 1] = h23;
}

// x rows: [ xh(256) | xh(256) | xl(256) ]
__global__ void vq_prep_x(const float* __restrict__ x) {
    int i = blockIdx.x * blockDim.x + threadIdx.x;
    if (i >= VQ_BT * (VQ_D / 4)) return;
    int t = i >> 6, d4 = i & 63;
    float4 v = reinterpret_cast<const float4*>(x)[i];
    uint32_t h01, h23, l01, l23;
    split4(v, h01, h23, l01, l23);
    uint32_t* row = g_xcat + (size_t)t * (KE / 2);
    row[d4 * 2]       = h01; row[d4 * 2 + 1]       = h23;
    row[128 + d4 * 2] = h01; row[128 + d4 * 2 + 1] = h23;
    row[256 + d4 * 2] = l01; row[256 + d4 * 2 + 1] = l23;
}

// ---------------------------------------------------------------------------
// B chunk loader: 128 codewords x 64 bf16 (128 B per row), SW128 swizzle.
// ---------------------------------------------------------------------------
__device__ __forceinline__ void loadB(uint32_t smB, int nt, int kc, int buf,
                                      int tid) {
    size_t src = __cvta_generic_to_global(g_ecat) + (size_t)nt * 1536 + kc * 128;
    uint32_t dstb = smB + buf * SMB_BYTES;
    #pragma unroll
    for (int i = 0; i < 4; i++) {
        int j = tid + i * NTH;        // 0..1023
        int n = j >> 3, cc = j & 7;
        uint32_t dst = dstb + n * 128 + ((cc * 16) ^ ((n & 7) << 4));
        cp16(dst, src + (size_t)n * 1536 + cc * 16);
    }
}

// ---------------------------------------------------------------------------
// Main kernel: 128 CTAs x 256 threads; 128 tokens/CTA.
// Warp grid 4(m) x 2(n); warp tile 32x64.
// ---------------------------------------------------------------------------
__global__ __launch_bounds__(NTH, 1) void vq_mma() {
    extern __shared__ char smc[];
    const uint32_t smA = smem_to_u32(smc);
    const uint32_t smB = smA + SMA_BYTES;
    const int tid  = threadIdx.x;
    const int lane = tid & 31;
    const int w    = tid >> 5;
    const int mw   = w & 3;          // 0..3 (m)
    const int nw   = w >> 2;         // 0..1 (n)
    const int m_base = blockIdx.x * BM;

    // ---- prologue loads: A tile + chunk0 (group0), chunk1 (group1) ----
    {
        size_t src = __cvta_generic_to_global(g_xcat) + (size_t)m_base * 1536;
        #pragma unroll
        for (int i = 0; i < 48; i++) {
            int j = tid + i * NTH;           // 0..12287
            int m = j / 96, c = j % 96;
            cp16(smA + m * ASTR + c * 16, src + (size_t)m * 1536 + c * 16);
        }
        loadB(smB, 0, 0, 0, tid);
        asm volatile("cp.async.commit_group;" ::: "memory");
        loadB(smB, 0, 1, 1, tid);
        asm volatile("cp.async.commit_group;" ::: "memory");
    }

    // ---- accumulators / running argmin ----
    float acc[2][8][4];
    #pragma unroll
    for (int a = 0; a < 2; a++)
        #pragma unroll
        for (int b = 0; b < 8; b++)
            #pragma unroll
            for (int c = 0; c < 4; c++) acc[a][b][c] = 0.f;
    float bv[4];
    int   bi[4];
    #pragma unroll
    for (int s = 0; s < 4; s++) { bv[s] = __int_as_float(0x7f7fffff); bi[s] = 0; }

    const uint32_t half  = (uint32_t)((lane >> 4) << 4);   // 0 | 16 bytes
    const uint32_t swb   = (uint32_t)((lane & 7) << 4);    // B swizzle XOR
    const uint32_t aRow  = smA + (mw * 32 + (lane & 15)) * ASTR;
    const uint32_t bRow0 = smB + (nw * 64 + (lane & 15)) * 128;

    uint32_t afr[2][2][4], bfr[2][4][4];

    auto ld_frags = [&](int s, uint32_t kaBytes, uint32_t bRow, uint32_t kbBytes) {
        uint32_t ka = kaBytes + half;
        uint32_t kb = (kbBytes + half) ^ swb;
        ldsm4(afr[s][0], aRow + ka);
        ldsm4(afr[s][1], aRow + 16 * ASTR + ka);
        ldsm4(bfr[s][0], bRow + kb);
        ldsm4(bfr[s][1], bRow + 2048 + kb);
        ldsm4(bfr[s][2], bRow + 4096 + kb);
        ldsm4(bfr[s][3], bRow + 6144 + kb);
    };
    auto mma_step = [&](int s) {
        #pragma unroll
        for (int mt = 0; mt < 2; mt++)
            #pragma unroll
            for (int np = 0; np < 4; np++) {
                mma16816(acc[mt][np * 2 + 0], afr[s][mt],
                         bfr[s][np][0], bfr[s][np][2]);
                mma16816(acc[mt][np * 2 + 1], afr[s][mt],
                         bfr[s][np][1], bfr[s][np][3]);
            }
    };

    // wait for group0 (A + chunk0), then preload chunk0 ks0 -> slot 0
    asm volatile("cp.async.wait_group 1;" ::: "memory");
    __syncthreads();
    ld_frags(0, 0, bRow0, 0);

    int kc = 0, nchunk = 0;
    #pragma unroll 1
    for (int c = 0; c < TOTCH; c++) {
        const uint32_t bRow = bRow0 + (uint32_t)(c & 1) * SMB_BYTES;
        const uint32_t kbase = (uint32_t)(kc * 128);

        // ks0 MMA (slot0 preloaded); ldsm ks1 -> slot1
        ld_frags(1, kbase + 32, bRow, 32);
        mma_step(0);
        // ks1 MMA (slot1); ldsm ks2 -> slot0
        ld_frags(0, kbase + 64, bRow, 64);
        mma_step(1);
        // ks2 MMA (slot0); ldsm ks3 -> slot1  (last read of this buffer)
        ld_frags(1, kbase + 96, bRow, 96);
        mma_step(0);

        // barrier: all warps done reading buf (c&1); then overwrite it with
        // chunk c+2. ks3 MMAs shadow the barrier cost.
        __syncthreads();
        if (c + 2 < TOTCH) {
            int k2 = kc + 2, n2 = nchunk;
            if (k2 >= KCH) { k2 -= KCH; n2++; }
            loadB(smB, n2 * BN, k2, c & 1, tid);
        }
        asm volatile("cp.async.commit_group;" ::: "memory");

        // ks3 MMA (slot1)
        mma_step(1);

        // chunk c+1 is in the other buffer; all but the newest group done.
        asm volatile("cp.async.wait_group 1;" ::: "memory");
        if (c + 1 < TOTCH) {
            int k1 = kc + 1;
            if (k1 == KCH) k1 = 0;
            const uint32_t bRowN = bRow0 + (uint32_t)((c + 1) & 1) * SMB_BYTES;
            ld_frags(0, (uint32_t)(k1 * 128), bRowN, 0);
        }

        // ---- end of n-chunk: fold argmin, reset acc ----
        if (kc == KCH - 1) {
            const int nb0 = nchunk * BN + nw * 64 + 2 * (lane & 3);
            #pragma unroll
            for (int nt = 0; nt < 8; nt++) {
                float c0 = __ldg(g_cnorm + nb0 + nt * 8);
                float c1 = __ldg(g_cnorm + nb0 + nt * 8 + 1);
                int nb = nb0 + nt * 8;
                #pragma unroll
                for (int mt = 0; mt < 2; mt++) {
                    int se = mt * 2, so = mt * 2 + 1;
                    float s0 = c0 - acc[mt][nt][0];
                    float s1 = c1 - acc[mt][nt][1];
                    float s2 = c0 - acc[mt][nt][2];
                    float s3 = c1 - acc[mt][nt][3];
                    if (s0 < bv[se]) { bv[se] = s0; bi[se] = nb; }
                    if (s1 < bv[se]) { bv[se] = s1; bi[se] = nb + 1; }
                    if (s2 < bv[so]) { bv[so] = s2; bi[so] = nb; }
                    if (s3 < bv[so]) { bv[so] = s3; bi[so] = nb + 1; }
                    acc[mt][nt][0] = 0.f; acc[mt][nt][1] = 0.f;
                    acc[mt][nt][2] = 0.f; acc[mt][nt][3] = 0.f;
                }
            }
        }

        if (++kc == KCH) { kc = 0; nchunk++; }
    }

    // ---- quad reduce (lanes sharing a row differ in bits 0-1) ----
    #pragma unroll
    for (int off = 1; off < 4; off <<= 1) {
        #pragma unroll
        for (int s = 0; s < 4; s++) {
            float ov = __shfl_xor_sync(0xffffffffu, bv[s], off);
            int   oi = __shfl_xor_sync(0xffffffffu, bi[s], off);
            if (ov < bv[s] || (ov == bv[s] && oi < bi[s])) { bv[s] = ov; bi[s] = oi; }
        }
    }

    // ---- cross-n-warp reduce via smem (reuse A region after barrier) ----
    __syncthreads();
    float* sv = reinterpret_cast<float*>(smc);
    int*   si = reinterpret_cast<int*>(smc + 1024);
    if ((lane & 3) == 0) {
        #pragma unroll
        for (int s = 0; s < 4; s++) {
            int row = mw * 32 + s * 8 + (lane >> 2);
            sv[row * 2 + nw] = bv[s];
            si[row * 2 + nw] = bi[s];
        }
    }
    __syncthreads();
    if (tid < BM) {
        float v0 = sv[tid * 2];     int i0 = si[tid * 2];
        float v1 = sv[tid * 2 + 1]; int i1 = si[tid * 2 + 1];
        if (v1 < v0 || (v1 == v0 && i1 < i0)) { v0 = v1; i0 = i1; }
        g_idx[m_base + tid] = i0;
    }
}

// ---------------------------------------------------------------------------
// Gather + loss (exact fp32)
// ---------------------------------------------------------------------------
__global__ void vq_gather(const float* __restrict__ x, const float* __restrict__ emb,
                          float* __restrict__ out_vals, float* __restrict__ out_idx,
                          int write_idx) {
    int t   = blockIdx.x;
    int tid = threadIdx.x;  // 0..63
    int idx = g_idx[t];
    float4 xv = reinterpret_cast<const float4*>(x)[(size_t)t * (VQ_D / 4) + tid];
    float4 ev = reinterpret_cast<const float4*>(emb)[(size_t)idx * (VQ_D / 4) + tid];
    float4 ov;
    ov.x = xv.x + (ev.x - xv.x);
    ov.y = xv.y + (ev.y - xv.y);
    ov.z = xv.z + (ev.z - xv.z);
    ov.w = xv.w + (ev.w - xv.w);
    reinterpret_cast<float4*>(out_vals)[(size_t)t * (VQ_D / 4) + tid] = ov;

    float dx = xv.x - ev.x, dy = xv.y - ev.y, dz = xv.z - ev.z, dw = xv.w - ev.w;
    float s = dx * dx + dy * dy + dz * dz + dw * dw;
    #pragma unroll
    for (int o = 16; o; o >>= 1) s += __shfl_xor_sync(0xffffffffu, s, o);
    __shared__ float ws[2];
    if ((tid & 31) == 0) ws[tid >> 5] = s;
    __syncthreads();
    if (tid == 0) {
        atomicAdd(&g_lossacc, (double)(ws[0] + ws[1]));
        if (write_idx) out_idx[t] = (float)idx;
    }
}

__global__ void vq_finalize(float* __restrict__ loss_out) {
    double mse = g_lossacc / (double)((size_t)VQ_BT * VQ_D);
    *loss_out = (float)((1.0 + BETA) * mse);
}

// ---------------------------------------------------------------------------
extern "C" void kernel_launch(void* const* d_in, const int* in_sizes, int n_in,
                              void* d_out, int out_size) {
    const float* x   = (const float*)d_in[0];
    const float* emb = (const float*)d_in[1];
    if (n_in >= 2 && in_sizes[0] < in_sizes[1]) {
        x   = (const float*)d_in[1];
        emb = (const float*)d_in[0];
    }

    float* out      = (float*)d_out;
    float* out_idx  = out + (size_t)VQ_BT * VQ_D;
    float* out_loss = out_idx + VQ_BT;
    int write_idx  = (out_size >= VQ_BT * VQ_D + VQ_BT);
    int write_loss = (out_size >= VQ_BT * VQ_D + VQ_BT + 1);

    vq_norms<<<VQ_K / 8, 256>>>(emb);
    vq_prep_emb<<<(VQ_K * (VQ_D / 4)) / 256, 256>>>(emb);
    vq_prep_x<<<(VQ_BT * (VQ_D / 4)) / 256, 256>>>(x);

    cudaFuncSetAttribute(vq_mma, cudaFuncAttributeMaxDynamicSharedMemorySize,
                         SM_TOTAL);
    vq_mma<<<VQ_BT / BM, NTH, SM_TOTAL>>>();

    vq_gather<<<VQ_BT, 64>>>(x, emb, out, out_idx, write_idx);
    if (write_loss) vq_finalize<<<1, 1>>>(out_loss);
}

// round 9
// speedup vs baseline: 1.2460x; 1.2460x over previous
#include <cuda_runtime.h>
#include <cuda_bf16.h>
#include <cstdint>
#include <cstddef>

// ===========================================================================
// VQ nearest-codebook via warp-level HMMA (mma.sync m16n8k16 bf16).
//   argmin_k ||x-e_k||^2 == argmin_k (0.5||e_k||^2 - x.e_k)
// dot via bf16 3-way split = K=768 GEMM  A'=[xh|xh|xl], B'=[eh|el|eh].
// R9: dedup storage (A=[xh|xl], B=[eh|el], 512 cols each) + per-chunk base
// remap; freed smem buys BK=256B -> 192 chunks (half the barriers of R6).
// Schedule identical to R6 (best); all intra-chunk offsets constant.
// ===========================================================================

#define VQ_D   256
#define VQ_K   4096
#define VQ_BT  16384
#define BETA   0.2

#define BM   128
#define BN   128
#define KCH  6                    // k-chunks per n-chunk (128 bf16 = 256 B each)
#define NCH  (VQ_K / BN)          // 32
#define TOTCH (NCH * KCH)         // 192
#define NTH  256

#define ASTR  1040                // A smem row stride bytes (65*16, data 1024)
#define BSTR  272                 // B smem row stride bytes (17*16, data 256)
#define SMA_BYTES (128 * ASTR)    // 133120
#define SMB_BYTES (128 * BSTR)    // 34816
#define SM_TOTAL (SMA_BYTES + 2 * SMB_BYTES)   // 202752 <= 232448

// ---------------- device globals -------------------------------------------
__device__ float    g_cnorm[VQ_K];
__device__ int      g_idx[VQ_BT];
__device__ double   g_lossacc;
__device__ uint32_t g_ecat[VQ_K * 256];     // [4096][512] bf16 = [eh|el]
__device__ uint32_t g_xcat[VQ_BT * 256];    // [16384][512] bf16 = [xh|xl]

// per-chunk base offsets (bytes) into the 512-col dedup storage
__constant__ int c_abase[6] = {0, 256, 0, 256, 512, 768};     // A: xh,xh,xl
__constant__ int c_bbase[6] = {0, 256, 512, 768, 0, 256};     // B: eh,el,eh

// ---------------- helpers ---------------------------------------------------
__device__ __forceinline__ uint32_t smem_to_u32(const void* p) {
    uint32_t a;
    asm("{ .reg .u64 t; cvta.to.shared.u64 t, %1; cvt.u32.u64 %0, t; }"
        : "=r"(a) : "l"(p));
    return a;
}
__device__ __forceinline__ void cp16(uint32_t dst, size_t gsrc) {
    asm volatile("cp.async.cg.shared.global [%0], [%1], 16;"
                 :: "r"(dst), "l"(gsrc));
}
__device__ __forceinline__ void ldsm4(uint32_t* r, uint32_t addr) {
    asm volatile("ldmatrix.sync.aligned.m8n8.x4.shared.b16 {%0,%1,%2,%3}, [%4];"
                 : "=r"(r[0]), "=r"(r[1]), "=r"(r[2]), "=r"(r[3]) : "r"(addr));
}
__device__ __forceinline__ void mma16816(float* c, const uint32_t* a,
                                         uint32_t b0, uint32_t b1) {
    asm volatile(
        "mma.sync.aligned.m16n8k16.row.col.f32.bf16.bf16.f32 "
        "{%0,%1,%2,%3}, {%4,%5,%6,%7}, {%8,%9}, {%0,%1,%2,%3};"
        : "+f"(c[0]), "+f"(c[1]), "+f"(c[2]), "+f"(c[3])
        : "r"(a[0]), "r"(a[1]), "r"(a[2]), "r"(a[3]), "r"(b0), "r"(b1));
}

// ---------------------------------------------------------------------------
// Prep kernels
// ---------------------------------------------------------------------------
__global__ void vq_norms(const float* __restrict__ emb) {
    if (blockIdx.x == 0 && threadIdx.x == 0) g_lossacc = 0.0;
    int warp = (blockIdx.x * blockDim.x + threadIdx.x) >> 5;
    int lane = threadIdx.x & 31;
    if (warp >= VQ_K) return;
    const float4* e4 = reinterpret_cast<const float4*>(emb) + (size_t)warp * (VQ_D / 4);
    float s = 0.f;
    #pragma unroll
    for (int i = lane; i < VQ_D / 4; i += 32) {
        float4 v = e4[i];
        s += v.x * v.x + v.y * v.y + v.z * v.z + v.w * v.w;
    }
    #pragma unroll
    for (int o = 16; o; o >>= 1) s += __shfl_xor_sync(0xffffffffu, s, o);
    if (lane == 0) g_cnorm[warp] = 0.5f * s;
}

__device__ __forceinline__ void split4(float4 v, uint32_t& h01, uint32_t& h23,
                                       uint32_t& l01, uint32_t& l23) {
    __nv_bfloat162 h, l;
    h.x = __float2bfloat16_rn(v.x);
    h.y = __float2bfloat16_rn(v.y);
    l.x = __float2bfloat16_rn(v.x - __bfloat162float(h.x));
    l.y = __float2bfloat16_rn(v.y - __bfloat162float(h.y));
    h01 = *reinterpret_cast<uint32_t*>(&h);
    l01 = *reinterpret_cast<uint32_t*>(&l);
    h.x = __float2bfloat16_rn(v.z);
    h.y = __float2bfloat16_rn(v.w);
    l.x = __float2bfloat16_rn(v.z - __bfloat162float(h.x));
    l.y = __float2bfloat16_rn(v.w - __bfloat162float(h.y));
    h23 = *reinterpret_cast<uint32_t*>(&h);
    l23 = *reinterpret_cast<uint32_t*>(&l);
}

// rows: [ hi(256) | lo(256) ]  (512 cols, dedup)
__global__ void vq_prep_emb(const float* __restrict__ emb) {
    int i = blockIdx.x * blockDim.x + threadIdx.x;
    if (i >= VQ_K * (VQ_D / 4)) return;
    int k = i >> 6, d4 = i & 63;
    float4 v = reinterpret_cast<const float4*>(emb)[i];
    uint32_t h01, h23, l01, l23;
    split4(v, h01, h23, l01, l23);
    uint32_t* row = g_ecat + (size_t)k * 256;
    row[d4 * 2]       = h01; row[d4 * 2 + 1]       = h23;
    row[128 + d4 * 2] = l01; row[128 + d4 * 2 + 1] = l23;
}

__global__ void vq_prep_x(const float* __restrict__ x) {
    int i = blockIdx.x * blockDim.x + threadIdx.x;
    if (i >= VQ_BT * (VQ_D / 4)) return;
    int t = i >> 6, d4 = i & 63;
    float4 v = reinterpret_cast<const float4*>(x)[i];
    uint32_t h01, h23, l01, l23;
    split4(v, h01, h23, l01, l23);
    uint32_t* row = g_xcat + (size_t)t * 256;
    row[d4 * 2]       = h01; row[d4 * 2 + 1]       = h23;
    row[128 + d4 * 2] = l01; row[128 + d4 * 2 + 1] = l23;
}

// ---------------------------------------------------------------------------
// B chunk loader: 128 codewords x 128 bf16 (256 B per row), stride 272.
// kc selects the global 256B window via c_bbase.
// ---------------------------------------------------------------------------
__device__ __forceinline__ void loadB(uint32_t smB, int nt, int kc, int buf,
                                      int tid) {
    size_t src = __cvta_generic_to_global(g_ecat) + (size_t)nt * 1024 + c_bbase[kc];
    uint32_t dstb = smB + buf * SMB_BYTES;
    #pragma unroll
    for (int i = 0; i < 8; i++) {
        int j = tid + i * NTH;        // 0..2047
        int n = j >> 4, cc = j & 15;
        cp16(dstb + n * BSTR + cc * 16, src + (size_t)n * 1024 + cc * 16);
    }
}

// ---------------------------------------------------------------------------
// Main kernel: 128 CTAs x 256 threads; 128 tokens/CTA.
// Warp grid 4(m) x 2(n); warp tile 32x64.
// ---------------------------------------------------------------------------
__global__ __launch_bounds__(NTH, 1) void vq_mma() {
    extern __shared__ char smc[];
    const uint32_t smA = smem_to_u32(smc);
    const uint32_t smB = smA + SMA_BYTES;
    const int tid  = threadIdx.x;
    const int lane = tid & 31;
    const int w    = tid >> 5;
    const int mw   = w & 3;          // 0..3 (m)
    const int nw   = w >> 2;         // 0..1 (n)
    const int m_base = blockIdx.x * BM;

    // ---- A tile load: 128 rows x 1024 B (stride 1040) + chunk 0 ----
    {
        size_t src = __cvta_generic_to_global(g_xcat) + (size_t)m_base * 1024;
        #pragma unroll
        for (int i = 0; i < 32; i++) {
            int j = tid + i * NTH;           // 0..8191
            int m = j >> 6, c = j & 63;
            cp16(smA + m * ASTR + c * 16, src + (size_t)m * 1024 + c * 16);
        }
        loadB(smB, 0, 0, 0, tid);
        asm volatile("cp.async.commit_group;" ::: "memory");
    }

    // ---- accumulators / running argmin ----
    float acc[2][8][4];
    #pragma unroll
    for (int a = 0; a < 2; a++)
        #pragma unroll
        for (int b = 0; b < 8; b++)
            #pragma unroll
            for (int c = 0; c < 4; c++) acc[a][b][c] = 0.f;
    float bv[4];
    int   bi[4];
    #pragma unroll
    for (int s = 0; s < 4; s++) { bv[s] = __int_as_float(0x7f7fffff); bi[s] = 0; }

    const uint32_t half  = (uint32_t)((lane >> 4) << 4);   // 0 | 16 bytes
    const uint32_t aRow  = smA + (mw * 32 + (lane & 15)) * ASTR;
    const uint32_t bRow0 = smB + (nw * 64 + (lane & 15)) * BSTR;

    int kc = 0, nchunk = 0;
    #pragma unroll 1
    for (int c = 0; c < TOTCH; c++) {
        const int buf = c & 1;

        asm volatile("cp.async.wait_group 0;" ::: "memory");
        __syncthreads();
        if (c + 1 < TOTCH) {
            int k1 = kc + 1, n1 = nchunk;
            if (k1 == KCH) { k1 = 0; n1++; }
            loadB(smB, n1 * BN, k1, (c + 1) & 1, tid);
            asm volatile("cp.async.commit_group;" ::: "memory");
        }

        // ---- compute chunk kc from buffer buf (8 k16 steps, dbl-buffered) --
        const uint32_t aBase = aRow + (uint32_t)c_abase[kc] + half;
        const uint32_t bRow  = bRow0 + buf * SMB_BYTES + half;
        uint32_t afr[2][2][4], bfr[2][4][4];
        {   // ks = 0
            ldsm4(afr[0][0], aBase);
            ldsm4(afr[0][1], aBase + 16 * ASTR);
            ldsm4(bfr[0][0], bRow);
            ldsm4(bfr[0][1], bRow + 16 * BSTR);
            ldsm4(bfr[0][2], bRow + 32 * BSTR);
            ldsm4(bfr[0][3], bRow + 48 * BSTR);
        }
        #pragma unroll
        for (int ks = 0; ks < 8; ks++) {
            const int cur = ks & 1, nxt = cur ^ 1;
            if (ks < 7) {
                uint32_t ka = aBase + (uint32_t)((ks + 1) * 32);
                uint32_t kb = bRow + (uint32_t)((ks + 1) * 32);
                ldsm4(afr[nxt][0], ka);
                ldsm4(afr[nxt][1], ka + 16 * ASTR);
                ldsm4(bfr[nxt][0], kb);
                ldsm4(bfr[nxt][1], kb + 16 * BSTR);
                ldsm4(bfr[nxt][2], kb + 32 * BSTR);
                ldsm4(bfr[nxt][3], kb + 48 * BSTR);
            }
            #pragma unroll
            for (int mt = 0; mt < 2; mt++)
                #pragma unroll
                for (int np = 0; np < 4; np++) {
                    mma16816(acc[mt][np * 2 + 0], afr[cur][mt],
                             bfr[cur][np][0], bfr[cur][np][2]);
                    mma16816(acc[mt][np * 2 + 1], afr[cur][mt],
                             bfr[cur][np][1], bfr[cur][np][3]);
                }
        }

        // ---- end of n-chunk: fold argmin, reset acc ----
        if (kc == KCH - 1) {
            const int nb0 = nchunk * BN + nw * 64 + 2 * (lane & 3);
            #pragma unroll
            for (int nt = 0; nt < 8; nt++) {
                float c0 = __ldg(g_cnorm + nb0 + nt * 8);
                float c1 = __ldg(g_cnorm + nb0 + nt * 8 + 1);
                int nb = nb0 + nt * 8;
                #pragma unroll
                for (int mt = 0; mt < 2; mt++) {
                    int se = mt * 2, so = mt * 2 + 1;
                    float s0 = c0 - acc[mt][nt][0];
                    float s1 = c1 - acc[mt][nt][1];
                    float s2 = c0 - acc[mt][nt][2];
                    float s3 = c1 - acc[mt][nt][3];
                    if (s0 < bv[se]) { bv[se] = s0; bi[se] = nb; }
                    if (s1 < bv[se]) { bv[se] = s1; bi[se] = nb + 1; }
                    if (s2 < bv[so]) { bv[so] = s2; bi[so] = nb; }
                    if (s3 < bv[so]) { bv[so] = s3; bi[so] = nb + 1; }
                    acc[mt][nt][0] = 0.f; acc[mt][nt][1] = 0.f;
                    acc[mt][nt][2] = 0.f; acc[mt][nt][3] = 0.f;
                }
            }
        }

        if (++kc == KCH) { kc = 0; nchunk++; }
    }

    // ---- quad reduce (lanes sharing a row differ in bits 0-1) ----
    #pragma unroll
    for (int off = 1; off < 4; off <<= 1) {
        #pragma unroll
        for (int s = 0; s < 4; s++) {
            float ov = __shfl_xor_sync(0xffffffffu, bv[s], off);
            int   oi = __shfl_xor_sync(0xffffffffu, bi[s], off);
            if (ov < bv[s] || (ov == bv[s] && oi < bi[s])) { bv[s] = ov; bi[s] = oi; }
        }
    }

    // ---- cross-n-warp reduce via smem (reuse A region after barrier) ----
    __syncthreads();
    float* sv = reinterpret_cast<float*>(smc);
    int*   si = reinterpret_cast<int*>(smc + 1024);
    if ((lane & 3) == 0) {
        #pragma unroll
        for (int s = 0; s < 4; s++) {
            int row = mw * 32 + s * 8 + (lane >> 2);
            sv[row * 2 + nw] = bv[s];
            si[row * 2 + nw] = bi[s];
        }
    }
    __syncthreads();
    if (tid < BM) {
        float v0 = sv[tid * 2];     int i0 = si[tid * 2];
        float v1 = sv[tid * 2 + 1]; int i1 = si[tid * 2 + 1];
        if (v1 < v0 || (v1 == v0 && i1 < i0)) { v0 = v1; i0 = i1; }
        g_idx[m_base + tid] = i0;
    }
}

// ---------------------------------------------------------------------------
// Gather + loss (exact fp32)
// ---------------------------------------------------------------------------
__global__ void vq_gather(const float* __restrict__ x, const float* __restrict__ emb,
                          float* __restrict__ out_vals, float* __restrict__ out_idx,
                          int write_idx) {
    int t   = blockIdx.x;
    int tid = threadIdx.x;  // 0..63
    int idx = g_idx[t];
    float4 xv = reinterpret_cast<const float4*>(x)[(size_t)t * (VQ_D / 4) + tid];
    float4 ev = reinterpret_cast<const float4*>(emb)[(size_t)idx * (VQ_D / 4) + tid];
    float4 ov;
    ov.x = xv.x + (ev.x - xv.x);
    ov.y = xv.y + (ev.y - xv.y);
    ov.z = xv.z + (ev.z - xv.z);
    ov.w = xv.w + (ev.w - xv.w);
    reinterpret_cast<float4*>(out_vals)[(size_t)t * (VQ_D / 4) + tid] = ov;

    float dx = xv.x - ev.x, dy = xv.y - ev.y, dz = xv.z - ev.z, dw = xv.w - ev.w;
    float s = dx * dx + dy * dy + dz * dz + dw * dw;
    #pragma unroll
    for (int o = 16; o; o >>= 1) s += __shfl_xor_sync(0xffffffffu, s, o);
    __shared__ float ws[2];
    if ((tid & 31) == 0) ws[tid >> 5] = s;
    __syncthreads();
    if (tid == 0) {
        atomicAdd(&g_lossacc, (double)(ws[0] + ws[1]));
        if (write_idx) out_idx[t] = (float)idx;
    }
}

__global__ void vq_finalize(float* __restrict__ loss_out) {
    double mse = g_lossacc / (double)((size_t)VQ_BT * VQ_D);
    *loss_out = (float)((1.0 + BETA) * mse);
}

// ---------------------------------------------------------------------------
extern "C" void kernel_launch(void* const* d_in, const int* in_sizes, int n_in,
                              void* d_out, int out_size) {
    const float* x   = (const float*)d_in[0];
    const float* emb = (const float*)d_in[1];
    if (n_in >= 2 && in_sizes[0] < in_sizes[1]) {
        x   = (const float*)d_in[1];
        emb = (const float*)d_in[0];
    }

    float* out      = (float*)d_out;
    float* out_idx  = out + (size_t)VQ_BT * VQ_D;
    float* out_loss = out_idx + VQ_BT;
    int write_idx  = (out_size >= VQ_BT * VQ_D + VQ_BT);
    int write_loss = (out_size >= VQ_BT * VQ_D + VQ_BT + 1);

    vq_norms<<<VQ_K / 8, 256>>>(emb);
    vq_prep_emb<<<(VQ_K * (VQ_D / 4)) / 256, 256>>>(emb);
    vq_prep_x<<<(VQ_BT * (VQ_D / 4)) / 256, 256>>>(x);

    cudaFuncSetAttribute(vq_mma, cudaFuncAttributeMaxDynamicSharedMemorySize,
                         SM_TOTAL);
    vq_mma<<<VQ_BT / BM, NTH, SM_TOTAL>>>();

    vq_gather<<<VQ_BT, 64>>>(x, emb, out, out_idx, write_idx);
    if (write_loss) vq_finalize<<<1, 1>>>(out_loss);
}